// round 6
// baseline (speedup 1.0000x reference)
#include <cuda_runtime.h>

#define N_NODES 20000
#define N_EDGES 320000
#define DIM_D   768
#define DIM_H   1024
#define SDIM    2000
#define E4      (N_EDGES / 4)
#define E2      (N_EDGES / 2)
#define BT      1024

// ---- scratch (static __device__ globals; zero-initialized at module load) ----
__device__ float g_v[DIM_D];
__device__ float g_s1;
__device__ float g_deg[N_NODES];   // re-zeroed in phase G for next replay
__device__ float g_dinv[N_NODES];
__device__ float g_q[N_NODES];
__device__ float g_p[N_NODES];
__device__ float g_q2[N_NODES];
__device__ float g_p2[N_NODES];
__device__ float g_att[N_NODES];   // att for n >= SDIM (blocks 1.. during select)
__device__ float g_att_s[SDIM];    // att[0:S) exactly as select saw them
__device__ float g_cutoff;
__device__ unsigned g_bar_count;   // returns to 0 after every barrier
__device__ unsigned g_bar_gen;     // monotonically increments (wrap-safe)

// ---------------------------------------------------------------------------
// Software grid barrier. Arrival count = gridDim.x; the launcher guarantees
// every launched block is simultaneously resident (occupancy-derived grid).
__device__ __forceinline__ void gridsync() {
    __threadfence();
    __syncthreads();
    if (threadIdx.x == 0) {
        unsigned gen = *(volatile unsigned*)&g_bar_gen;   // read BEFORE arriving
        if (atomicAdd(&g_bar_count, 1u) == gridDim.x - 1) {
            atomicExch(&g_bar_count, 0u);
            __threadfence();
            atomicAdd(&g_bar_gen, 1u);
        } else {
            while (*(volatile unsigned*)&g_bar_gen == gen) { __nanosleep(64); }
        }
    }
    __syncthreads();
}

// ---------------------------------------------------------------------------
__global__ void __launch_bounds__(BT, 1)
k_all(const float* __restrict__ x, const int* __restrict__ row,
      const int* __restrict__ col, const float* __restrict__ ew,
      const int* __restrict__ y, const float* __restrict__ W1,
      const float* __restrict__ b1, const float* __restrict__ W2,
      const float* __restrict__ b2, float* __restrict__ out,
      int off, int write_loss) {
    __shared__ float sv[DIM_D];
    __shared__ float s_val[SDIM];
    __shared__ float s_t[SDIM];
    __shared__ float s_rv[32];
    __shared__ int   s_ri[32];
    __shared__ int   s_k;
    __shared__ float s_cut;

    const int tid   = threadIdx.x;
    const int g     = blockIdx.x * BT + tid;
    const int lane  = tid & 31;
    const int nthr  = gridDim.x * BT;
    const int nwarp = nthr >> 5;
    const int gw    = g >> 5;          // global warp id

    // ===== Phase A: v = W1@W2 (one warp/row), s1 = b1.W2, deg scatter, zero p/p2
    for (int r0 = gw; r0 <= DIM_D; r0 += nwarp) {
        const float* rowp = (r0 < DIM_D) ? (W1 + (size_t)r0 * DIM_H) : b1;
        const float4* rp = (const float4*)rowp;
        const float4* w2 = (const float4*)W2;
        float s = 0.f;
        #pragma unroll
        for (int i = lane; i < DIM_H / 4; i += 32) {
            float4 a = rp[i];
            float4 b = w2[i];
            s += a.x * b.x + a.y * b.y + a.z * b.z + a.w * b.w;
        }
        #pragma unroll
        for (int o = 16; o; o >>= 1) s += __shfl_xor_sync(0xffffffffu, s, o);
        if (!lane) { if (r0 < DIM_D) g_v[r0] = s; else g_s1 = s; }
    }
    for (int i = g; i < E4; i += nthr) {
        int4   c = ((const int4*)col)[i];
        float4 w = ((const float4*)ew)[i];
        atomicAdd(&g_deg[c.x], w.x);
        atomicAdd(&g_deg[c.y], w.y);
        atomicAdd(&g_deg[c.z], w.z);
        atomicAdd(&g_deg[c.w], w.w);
    }
    for (int i = g; i < N_NODES; i += nthr) { g_p[i] = 0.f; g_p2[i] = 0.f; }

    gridsync();

    // ===== Phase B: dinv = rsqrt(deg+1); q = dinv * (x[n,:].v)   (1 warp/node)
    for (int i = tid; i < DIM_D; i += BT) sv[i] = g_v[i];
    __syncthreads();
    {
        const float4* svv = (const float4*)sv;
        for (int n = gw; n < N_NODES; n += nwarp) {
            const float4* xr = (const float4*)(x + (size_t)n * DIM_D);
            float sum = 0.f;
            #pragma unroll
            for (int i = lane; i < DIM_D / 4; i += 32) {
                float4 a = __ldcs(&xr[i]);   // streaming: keep edges L2-resident
                float4 b = svv[i];
                sum += a.x * b.x + a.y * b.y + a.z * b.z + a.w * b.w;
            }
            #pragma unroll
            for (int o = 16; o; o >>= 1) sum += __shfl_xor_sync(0xffffffffu, sum, o);
            if (!lane) {
                float di = rsqrtf(g_deg[n] + 1.0f);
                g_dinv[n] = di;
                g_q[n] = di * sum;
            }
        }
    }

    gridsync();

    // ===== Phase C: p[c] += w * q[r]
    for (int i = g; i < E2; i += nthr) {
        int2   r = ((const int2*)row)[i];
        int2   c = ((const int2*)col)[i];
        float2 w = ((const float2*)ew)[i];
        float a = w.x * g_q[r.x];
        float b = w.y * g_q[r.y];
        atomicAdd(&g_p[c.x], a);
        atomicAdd(&g_p[c.y], b);
    }

    gridsync();

    // ===== Phase D: q2 = dinv * (dinv*(p+q) + s1)
    {
        float s1 = g_s1;
        for (int n = g; n < N_NODES; n += nthr) {
            float di = g_dinv[n];
            g_q2[n] = di * (di * (g_p[n] + g_q[n]) + s1);
        }
    }

    gridsync();

    // ===== Phase E: p2[c] += w * q2[r]
    for (int i = g; i < E2; i += nthr) {
        int2   r = ((const int2*)row)[i];
        int2   c = ((const int2*)col)[i];
        float2 w = ((const float2*)ew)[i];
        float a = w.x * g_q2[r.x];
        float b = w.y * g_q2[r.y];
        atomicAdd(&g_p2[c.x], a);
        atomicAdd(&g_p2[c.y], b);
    }

    gridsync();

    // ===== Phase F: block 0 -> select (k, cutoff, loss); others -> att[n>=SDIM]
    if (blockIdx.x == 0) {
        if (tid == 0) s_k = 0;
        float bb = b2[0];
        for (int i = tid; i < SDIM; i += BT) {
            float a = g_dinv[i] * (g_p2[i] + g_q2[i]) + bb;
            s_val[i] = a;
            g_att_s[i] = a;               // exact bits reused by mask phase
            s_t[i] = 0.f;
        }
        __syncthreads();

        int kc = 0;
        for (int j = tid; j < SDIM; j += BT) {
            int yy = y[j];
            kc += (yy >= 0);
            if (yy > 0) s_t[yy] = 1.0f;   // idempotent; races benign
        }
        #pragma unroll
        for (int o = 16; o; o >>= 1) kc += __shfl_xor_sync(0xffffffffu, kc, o);
        if (!lane) atomicAdd(&s_k, kc);
        __syncthreads();
        int k = max(s_k, 1);

        // loss accumulation BEFORE destructive selection
        float acc = 0.f;
        for (int j = tid; j < SDIM; j += BT) {
            float v = s_val[j], t = s_t[j];
            float lp = log1pf(expf(-fabsf(v)));
            acc += t * (fminf(v, 0.f) - lp) + (1.f - t) * (fminf(-v, 0.f) - lp);
        }

        // k iterative (val, idx) argmax; remove one instance per round
        for (int it = 0; it < k; it++) {
            float bv = -3.4e38f;
            int   bi = SDIM;
            for (int j = tid; j < SDIM; j += BT) {
                float v = s_val[j];
                if (v > bv) { bv = v; bi = j; }
            }
            #pragma unroll
            for (int o = 16; o; o >>= 1) {
                float ov = __shfl_xor_sync(0xffffffffu, bv, o);
                int   oi = __shfl_xor_sync(0xffffffffu, bi, o);
                if (ov > bv || (ov == bv && oi < bi)) { bv = ov; bi = oi; }
            }
            if (!lane) { s_rv[tid >> 5] = bv; s_ri[tid >> 5] = bi; }
            __syncthreads();
            if (tid < 32) {
                bv = s_rv[tid]; bi = s_ri[tid];
                #pragma unroll
                for (int o = 16; o; o >>= 1) {
                    float ov = __shfl_xor_sync(0xffffffffu, bv, o);
                    int   oi = __shfl_xor_sync(0xffffffffu, bi, o);
                    if (ov > bv || (ov == bv && oi < bi)) { bv = ov; bi = oi; }
                }
                if (tid == 0) { s_cut = bv; s_val[bi] = -3.4e38f; }
            }
            __syncthreads();
        }
        if (tid == 0) g_cutoff = s_cut;

        #pragma unroll
        for (int o = 16; o; o >>= 1) acc += __shfl_xor_sync(0xffffffffu, acc, o);
        if (!lane) s_rv[tid >> 5] = acc;
        __syncthreads();
        if (tid == 0 && write_loss) {
            float tot = 0.f;
            #pragma unroll
            for (int w = 0; w < 32; w++) tot += s_rv[w];
            out[0] = -tot / (float)SDIM;
        }
    } else {
        float bb = b2[0];
        int i0 = SDIM + (blockIdx.x - 1) * BT + tid;
        int stride = (gridDim.x - 1) * BT;
        for (int n = i0; n < N_NODES; n += stride)
            g_att[n] = g_dinv[n] * (g_p2[n] + g_q2[n]) + bb;
    }

    gridsync();

    // ===== Phase G: mask write + deg re-zero for next replay
    {
        float cut = g_cutoff;
        for (int n = g; n < N_NODES; n += nthr) {
            float a = (n < SDIM) ? g_att_s[n] : g_att[n];
            out[off + n] = (a >= cut) ? 1.0f : 0.0f;
            g_deg[n] = 0.f;
        }
    }
}

// ---------------------------------------------------------------------------
extern "C" void kernel_launch(void* const* d_in, const int* in_sizes, int n_in,
                              void* d_out, int out_size) {
    const float* x  = (const float*)d_in[0];
    const int*   ei = (const int*)d_in[1];
    const float* ew = (const float*)d_in[2];
    const int*   y  = (const int*)d_in[3];
    const float* W1 = (const float*)d_in[4];
    const float* b1 = (const float*)d_in[5];
    const float* W2 = (const float*)d_in[6];
    const float* b2 = (const float*)d_in[7];
    const int* row = ei;             // edge_index[0,:]
    const int* col = ei + N_EDGES;   // edge_index[1,:]
    float* out = (float*)d_out;
    int off = (out_size > N_NODES) ? (out_size - N_NODES) : 0;  // expect 1

    // Deadlock-proof grid: every launched block must be simultaneously
    // resident. Query occupancy at capture time; grid dim is baked into
    // the graph (deterministic across replays).
    int dev = 0, sms = 0, occ = 0;
    cudaGetDevice(&dev);
    cudaDeviceGetAttribute(&sms, cudaDevAttrMultiProcessorCount, dev);
    cudaOccupancyMaxActiveBlocksPerMultiprocessor(&occ, k_all, BT, 0);
    int nblk = sms * (occ > 0 ? occ : 1);
    if (nblk > sms) nblk = sms;      // 1 block/SM is plenty (full threads/SM)
    if (nblk < 2) nblk = 2;

    k_all<<<nblk, BT>>>(x, row, col, ew, y, W1, b1, W2, b2, out,
                        off, off >= 1 ? 1 : 0);
}

// round 8
// speedup vs baseline: 1.3868x; 1.3868x over previous
#include <cuda_runtime.h>

#define N_NODES 20000
#define N_EDGES 320000
#define DIM_D   768
#define DIM_H   1024
#define SDIM    2000
#define VB      (DIM_D + 1)              // blocks for v/s1 computation
#define E4      (N_EDGES / 4)            // deg pass quads
#define EB4     ((E4 + 255) / 256)
#define E2      (N_EDGES / 2)            // edge pairs
#define EB2     ((E2 + 255) / 256)
#define NB      ((N_NODES + 255) / 256)

// ---- scratch (static __device__ globals; zero-initialized at module load) ----
__device__ float  g_v[DIM_D];      // W1 @ W2
__device__ float  g_s1;            // b1 . W2
__device__ float  g_deg[N_NODES];  // re-zeroed by k_mask each run (replay-safe)
__device__ float4 g_node[N_NODES]; // {x=dinv, y=q, z=p, w=p2}; z,w zeroed by k_z
__device__ float  g_att_s[SDIM];   // att[0:S) exactly as k_select saw them
__device__ float  g_cutoff;

// q2[n] from the node struct — single expression shared by edge2/select/mask
// so recomputation is bit-identical everywhere.
__device__ __forceinline__ float node_q2(float4 gi, float s1) {
    return gi.x * (gi.x * (gi.z + gi.y) + s1);
}

// ---------------------------------------------------------------------------
// Merged: blocks [0,VB): v[d] = W1[d,:].W2 (block DIM_D: s1 = b1.W2)
//         blocks [VB, VB+EB4): deg scatter, 4 edges/thread
__global__ void k_vdeg(const float* __restrict__ W1, const float* __restrict__ W2,
                       const float* __restrict__ b1,
                       const int* __restrict__ col, const float* __restrict__ ew) {
    if (blockIdx.x < VB) {
        int d = blockIdx.x;
        const float* rowp = (d < DIM_D) ? (W1 + (size_t)d * DIM_H) : b1;
        const float4* rp = (const float4*)rowp;
        const float4* w2 = (const float4*)W2;
        float s = 0.f;
        int lane = threadIdx.x & 31;
        int warp = threadIdx.x >> 5;
        for (int i = warp * 32 + lane; i < DIM_H / 4; i += 256)
            { float4 a = rp[i]; float4 b = w2[i];
              s += a.x * b.x + a.y * b.y + a.z * b.z + a.w * b.w; }
        #pragma unroll
        for (int o = 16; o; o >>= 1) s += __shfl_xor_sync(0xffffffffu, s, o);
        __shared__ float red[8];
        if (!lane) red[warp] = s;
        __syncthreads();
        if (threadIdx.x == 0) {
            float t = 0.f;
            #pragma unroll
            for (int w = 0; w < 8; w++) t += red[w];
            if (d < DIM_D) g_v[d] = t; else g_s1 = t;
        }
    } else {
        int i = (blockIdx.x - VB) * 256 + threadIdx.x;
        if (i < E4) {
            int4   c = ((const int4*)col)[i];
            float4 w = ((const float4*)ew)[i];
            atomicAdd(&g_deg[c.x], w.x);
            atomicAdd(&g_deg[c.y], w.y);
            atomicAdd(&g_deg[c.z], w.z);
            atomicAdd(&g_deg[c.w], w.w);
        }
    }
}

// ---------------------------------------------------------------------------
// One warp per node: dinv = rsqrt(deg+1); q = dinv*(x[n,:].v);
// single float4 store also zeroes p/p2 for this run.
__global__ void k_z(const float* __restrict__ x) {
    __shared__ float sv[DIM_D];
    for (int i = threadIdx.x; i < DIM_D; i += blockDim.x) sv[i] = g_v[i];
    __syncthreads();
    int warp = threadIdx.x >> 5, lane = threadIdx.x & 31;
    int n = blockIdx.x * (blockDim.x >> 5) + warp;
    if (n >= N_NODES) return;
    const float4* xr = (const float4*)(x + (size_t)n * DIM_D);
    const float4* vv = (const float4*)sv;
    float sum = 0.f;
    #pragma unroll
    for (int i = lane; i < DIM_D / 4; i += 32) {
        float4 a = __ldcs(&xr[i]);      // streaming: keep edges L2-resident
        float4 b = vv[i];
        sum += a.x * b.x + a.y * b.y + a.z * b.z + a.w * b.w;
    }
    #pragma unroll
    for (int o = 16; o; o >>= 1) sum += __shfl_xor_sync(0xffffffffu, sum, o);
    if (!lane) {
        float di = rsqrtf(g_deg[n] + 1.0f);
        g_node[n] = make_float4(di, di * sum, 0.f, 0.f);
    }
}

// ---------------------------------------------------------------------------
// p[c] += w * q[r]   (2 edges/thread; q via 16B node gather, atomic to .z)
__global__ void k_edge1(const int* __restrict__ row, const int* __restrict__ col,
                        const float* __restrict__ ew) {
    int i = blockIdx.x * blockDim.x + threadIdx.x;
    if (i >= E2) return;
    int2   r = ((const int2*)row)[i];
    int2   c = ((const int2*)col)[i];
    float2 w = ((const float2*)ew)[i];
    float* nf = (float*)g_node;
    float a = w.x * g_node[r.x].y;
    float b = w.y * g_node[r.y].y;
    atomicAdd(&nf[4 * c.x + 2], a);
    atomicAdd(&nf[4 * c.y + 2], b);
}

// ---------------------------------------------------------------------------
// p2[c] += w * q2[r], q2 computed on the fly from one 16B gather of node r.
__global__ void k_edge2(const int* __restrict__ row, const int* __restrict__ col,
                        const float* __restrict__ ew) {
    int i = blockIdx.x * blockDim.x + threadIdx.x;
    if (i >= E2) return;
    float s1 = g_s1;
    int2   r = ((const int2*)row)[i];
    int2   c = ((const int2*)col)[i];
    float2 w = ((const float2*)ew)[i];
    float* nf = (float*)g_node;
    float a = w.x * node_q2(g_node[r.x], s1);
    float b = w.y * node_q2(g_node[r.y], s1);
    atomicAdd(&nf[4 * c.x + 3], a);
    atomicAdd(&nf[4 * c.y + 3], b);
}

// ---------------------------------------------------------------------------
// att[n] = dinv*(p2 + q2) + b2.
// Single block: k = count(y>=0); cutoff = k-th largest of att[:S]; loss.
__global__ void k_select(const int* __restrict__ y, const float* __restrict__ b2,
                         float* __restrict__ out, int write_loss) {
    __shared__ float s_val[SDIM];
    __shared__ float s_t[SDIM];
    __shared__ int   s_k;
    __shared__ float s_rv[32];
    __shared__ int   s_ri[32];
    __shared__ float s_cut;
    int tid = threadIdx.x;
    if (tid == 0) s_k = 0;
    float bb = b2[0];
    float s1 = g_s1;
    for (int i = tid; i < SDIM; i += 1024) {
        float4 gi = g_node[i];
        float a = gi.x * (gi.w + node_q2(gi, s1)) + bb;
        s_val[i] = a;
        g_att_s[i] = a;           // exact bits reused by k_mask
        s_t[i] = 0.f;
    }
    __syncthreads();

    int kc = 0;
    for (int j = tid; j < SDIM; j += 1024) {
        int yy = y[j];
        kc += (yy >= 0);
        if (yy > 0) s_t[yy] = 1.0f;   // idempotent; races benign
    }
    #pragma unroll
    for (int o = 16; o; o >>= 1) kc += __shfl_xor_sync(0xffffffffu, kc, o);
    if ((tid & 31) == 0) atomicAdd(&s_k, kc);
    __syncthreads();
    int k = max(s_k, 1);

    // loss accumulation BEFORE destructive selection
    float acc = 0.f;
    for (int j = tid; j < SDIM; j += 1024) {
        float v = s_val[j], t = s_t[j];
        float lp = log1pf(expf(-fabsf(v)));
        acc += t * (fminf(v, 0.f) - lp) + (1.f - t) * (fminf(-v, 0.f) - lp);
    }

    // k iterative (val, idx) argmax; remove one instance per round
    for (int it = 0; it < k; it++) {
        float bv = -3.4e38f;
        int   bi = SDIM;
        for (int j = tid; j < SDIM; j += 1024) {
            float v = s_val[j];
            if (v > bv) { bv = v; bi = j; }
        }
        #pragma unroll
        for (int o = 16; o; o >>= 1) {
            float ov = __shfl_xor_sync(0xffffffffu, bv, o);
            int   oi = __shfl_xor_sync(0xffffffffu, bi, o);
            if (ov > bv || (ov == bv && oi < bi)) { bv = ov; bi = oi; }
        }
        if ((tid & 31) == 0) { s_rv[tid >> 5] = bv; s_ri[tid >> 5] = bi; }
        __syncthreads();
        if (tid < 32) {
            bv = s_rv[tid]; bi = s_ri[tid];
            #pragma unroll
            for (int o = 16; o; o >>= 1) {
                float ov = __shfl_xor_sync(0xffffffffu, bv, o);
                int   oi = __shfl_xor_sync(0xffffffffu, bi, o);
                if (ov > bv || (ov == bv && oi < bi)) { bv = ov; bi = oi; }
            }
            if (tid == 0) { s_cut = bv; s_val[bi] = -3.4e38f; }
        }
        __syncthreads();
    }
    if (tid == 0) g_cutoff = s_cut;

    // loss reduction
    #pragma unroll
    for (int o = 16; o; o >>= 1) acc += __shfl_xor_sync(0xffffffffu, acc, o);
    if ((tid & 31) == 0) s_rv[tid >> 5] = acc;
    __syncthreads();
    if (tid == 0 && write_loss) {
        float tot = 0.f;
        #pragma unroll
        for (int w = 0; w < 32; w++) tot += s_rv[w];
        out[0] = -tot / (float)SDIM;
    }
}

// ---------------------------------------------------------------------------
// mask write; side work: re-zero g_deg so the next replay starts clean
__global__ void k_mask(const float* __restrict__ b2, float* __restrict__ out, int off) {
    int n = blockIdx.x * blockDim.x + threadIdx.x;
    if (n >= N_NODES) return;
    float a;
    if (n < SDIM) {
        a = g_att_s[n];                      // identical bits to k_select
    } else {
        float4 gi = g_node[n];
        a = gi.x * (gi.w + node_q2(gi, g_s1)) + b2[0];
    }
    out[off + n] = (a >= g_cutoff) ? 1.0f : 0.0f;
    g_deg[n] = 0.f;
}

// ---------------------------------------------------------------------------
extern "C" void kernel_launch(void* const* d_in, const int* in_sizes, int n_in,
                              void* d_out, int out_size) {
    const float* x  = (const float*)d_in[0];
    const int*   ei = (const int*)d_in[1];
    const float* ew = (const float*)d_in[2];
    const int*   y  = (const int*)d_in[3];
    const float* W1 = (const float*)d_in[4];
    const float* b1 = (const float*)d_in[5];
    const float* W2 = (const float*)d_in[6];
    const float* b2 = (const float*)d_in[7];
    const int* row = ei;             // edge_index[0,:]
    const int* col = ei + N_EDGES;   // edge_index[1,:]
    float* out = (float*)d_out;
    int off = (out_size > N_NODES) ? (out_size - N_NODES) : 0;  // expect 1

    k_vdeg<<<VB + EB4, 256>>>(W1, W2, b1, col, ew);
    k_z<<<(N_NODES + 7) / 8, 256>>>(x);
    k_edge1<<<EB2, 256>>>(row, col, ew);
    k_edge2<<<EB2, 256>>>(row, col, ew);
    k_select<<<1, 1024>>>(y, b2, out, off >= 1 ? 1 : 0);
    k_mask<<<NB, 256>>>(b2, out, off);
}